// round 1
// baseline (speedup 1.0000x reference)
#include <cuda_runtime.h>
#include <cstdint>

// GraphConv: y[b,o,n,t] = sum_f W[o,f] * h[b,f,n,t] + bias[o]
//   h = concat([x, x·A0, x·A0², x·A1, x·A1²], channel axis)
// Strategy:
//   prep: A0², A1² (tiny GEMM), Gt[j=(k,w)][v] = M_k[v][w]  (4 ops x 512x512, transposed)
//   transpose: Hfull[b][n][t][0:64] = x[b][:,n,t]
//   GEMM1 (103 GF): per (b,t): Out[j][c] = sum_v Gt[j][v]*Hfull[b][v][t][c]
//                   -> Hfull[b][w][t][64+64k+c]   (f32x2 packed FMA)
//   GEMM2 (16 GF):  y = Hfull[M=393216,320] @ Wt[320,64] + bias, coalesced scatter
// All scratch in __device__ globals (no allocation). All launches default-stream,
// graph-capturable, deterministic.

constexpr int Bdim = 64, Cdim = 64, Ndim = 512, Tdim = 12;
constexpr int CCAT = 320, COUT = 64;
constexpr int NT   = Ndim * Tdim;     // 6144
constexpr int KDIF = 4 * Ndim;        // 2048

__device__ float g_Hfull[(size_t)Bdim * NT * CCAT];   // 125,829,120 floats (~503 MB)
__device__ float g_Gt[(size_t)KDIF * Ndim];           // 4 MB
__device__ float g_A2[2 * Ndim * Ndim];               // 2 MB
__device__ float g_Wt[CCAT * COUT];                   // 80 KB

// ---------- packed f32x2 helpers (Blackwell FFMA2 path) ----------
__device__ __forceinline__ uint64_t pack2(float lo, float hi) {
    uint64_t p;
    asm("mov.b64 %0, {%1, %2};" : "=l"(p) : "f"(lo), "f"(hi));
    return p;
}
__device__ __forceinline__ float2 unpack2(uint64_t p) {
    float2 r;
    asm("mov.b64 {%0, %1}, %2;" : "=f"(r.x), "=f"(r.y) : "l"(p));
    return r;
}
__device__ __forceinline__ void fma2(uint64_t& d, uint64_t a, uint64_t b) {
    asm("fma.rn.f32x2 %0, %1, %2, %0;" : "+l"(d) : "l"(a), "l"(b));
}

// ---------- prep: A2[e] = A_e @ A_e ----------
__global__ __launch_bounds__(256) void a2_kernel(const float* __restrict__ S) {
    const int e = blockIdx.z;
    const float* __restrict__ A = S + e * Ndim * Ndim;
    const int r0 = blockIdx.y * 64, c0 = blockIdx.x * 64;
    __shared__ float As[16][64];
    __shared__ float Bs[16][64];
    const int tid = threadIdx.x;
    const int ty = tid >> 4, tx = tid & 15;
    float acc[4][4];
#pragma unroll
    for (int i = 0; i < 4; i++)
#pragma unroll
        for (int j = 0; j < 4; j++) acc[i][j] = 0.f;

    const int rrL = tid >> 2, k4L = (tid & 3) << 2;
    const int kkL = tid >> 4, c4L = (tid & 15) << 2;
    for (int k0 = 0; k0 < Ndim; k0 += 16) {
        float4 av = *reinterpret_cast<const float4*>(A + (r0 + rrL) * Ndim + k0 + k4L);
        As[k4L + 0][rrL] = av.x; As[k4L + 1][rrL] = av.y;
        As[k4L + 2][rrL] = av.z; As[k4L + 3][rrL] = av.w;
        *reinterpret_cast<float4*>(&Bs[kkL][c4L]) =
            *reinterpret_cast<const float4*>(A + (k0 + kkL) * Ndim + c0 + c4L);
        __syncthreads();
#pragma unroll
        for (int kk = 0; kk < 16; kk++) {
            float a[4], bb[4];
#pragma unroll
            for (int i = 0; i < 4; i++) a[i] = As[kk][ty * 4 + i];
#pragma unroll
            for (int j = 0; j < 4; j++) bb[j] = Bs[kk][tx * 4 + j];
#pragma unroll
            for (int i = 0; i < 4; i++)
#pragma unroll
                for (int j = 0; j < 4; j++) acc[i][j] += a[i] * bb[j];
        }
        __syncthreads();
    }
#pragma unroll
    for (int i = 0; i < 4; i++) {
        float4 v = make_float4(acc[i][0], acc[i][1], acc[i][2], acc[i][3]);
        *reinterpret_cast<float4*>(g_A2 + (size_t)e * Ndim * Ndim +
                                   (r0 + ty * 4 + i) * Ndim + c0 + tx * 4) = v;
    }
}

// ---------- prep: Gt[j=(k*512+w)][v] = M_k[v][w]; k in {A0, A0^2, A1, A1^2} ----------
__global__ __launch_bounds__(256) void gt_kernel(const float* __restrict__ S) {
    const int k = blockIdx.z;
    const float* __restrict__ M = (k == 0) ? S
                                : (k == 1) ? g_A2
                                : (k == 2) ? (S + Ndim * Ndim)
                                           : (g_A2 + Ndim * Ndim);
    const int v0 = blockIdx.y * 32, w0 = blockIdx.x * 32;
    __shared__ float s[32][33];
    const int ty = threadIdx.x >> 5, tx = threadIdx.x & 31;   // 8 x 32
#pragma unroll
    for (int i = 0; i < 4; i++)
        s[ty + i * 8][tx] = M[(v0 + ty + i * 8) * Ndim + w0 + tx];
    __syncthreads();
#pragma unroll
    for (int i = 0; i < 4; i++)
        g_Gt[(size_t)(k * Ndim + w0 + ty + i * 8) * Ndim + v0 + tx] = s[tx][ty + i * 8];
}

// ---------- prep: Wt[f][o] = W[o][f] ----------
__global__ void wt_kernel(const float* __restrict__ W) {
    int i = blockIdx.x * 256 + threadIdx.x;
    if (i < CCAT * COUT) {
        int f = i >> 6, o = i & 63;
        g_Wt[i] = W[o * CCAT + f];
    }
}

// ---------- transpose: Hfull[b][n][t][c] = x[b][c][n][t]  (identity block) ----------
__global__ __launch_bounds__(256) void transpose_kernel(const float* __restrict__ x) {
    __shared__ float s[64][97];
    const int b = blockIdx.y;
    const int n0 = blockIdx.x * 8;
    const int tid = threadIdx.x;
    for (int i = tid; i < 64 * 96; i += 256) {
        int c = i / 96, r = i - c * 96;  // r = dn*12 + t over 8 nodes x 12 steps
        s[c][r] = x[((size_t)(b * 64 + c) * Ndim + n0) * Tdim + r];
    }
    __syncthreads();
    for (int i = tid; i < 96 * 64; i += 256) {
        int r = i >> 6, c = i & 63;
        g_Hfull[((size_t)b * NT + n0 * Tdim + r) * CCAT + c] = s[c][r];
    }
}

// ---------- GEMM1: diffusion, per (b,t): Out[j][c] = sum_v Gt[j][v] * X[v][c] ----------
// Mtile=256 (j), Ntile=64 (c), K=512, Kt=16; 256 threads, 8x8 per thread, f32x2 FMA.
__global__ __launch_bounds__(256, 2) void gemm1_kernel() {
    const int bt = blockIdx.y;
    const int b = bt / Tdim, t = bt - b * Tdim;
    const int j0 = blockIdx.x * 256;
    __shared__ float As[16][256];
    __shared__ float Bs[16][64];
    const int tid = threadIdx.x;
    const int tm = tid >> 3, tn = tid & 7;

    uint64_t acc[8][4];
#pragma unroll
    for (int i = 0; i < 8; i++)
#pragma unroll
        for (int q = 0; q < 4; q++) acc[i][q] = 0ull;

    const float* __restrict__ Arow = g_Gt + (size_t)(j0 + tid) * Ndim;
    const int vvB = tid >> 4;
    const int c4B = (tid & 15) << 2;
    const float* __restrict__ Bp =
        g_Hfull + ((size_t)b * NT + t) * CCAT + (size_t)vvB * (Tdim * CCAT) + c4B;

    // software-pipelined prefetch (hide L2 latency under compute)
    float4 pa0 = *reinterpret_cast<const float4*>(Arow + 0);
    float4 pa1 = *reinterpret_cast<const float4*>(Arow + 4);
    float4 pa2 = *reinterpret_cast<const float4*>(Arow + 8);
    float4 pa3 = *reinterpret_cast<const float4*>(Arow + 12);
    float4 pb  = *reinterpret_cast<const float4*>(Bp);

    for (int k0 = 0; k0 < Ndim; k0 += 16) {
        As[0][tid]  = pa0.x; As[1][tid]  = pa0.y; As[2][tid]  = pa0.z; As[3][tid]  = pa0.w;
        As[4][tid]  = pa1.x; As[5][tid]  = pa1.y; As[6][tid]  = pa1.z; As[7][tid]  = pa1.w;
        As[8][tid]  = pa2.x; As[9][tid]  = pa2.y; As[10][tid] = pa2.z; As[11][tid] = pa2.w;
        As[12][tid] = pa3.x; As[13][tid] = pa3.y; As[14][tid] = pa3.z; As[15][tid] = pa3.w;
        *reinterpret_cast<float4*>(&Bs[vvB][c4B]) = pb;
        __syncthreads();
        if (k0 + 16 < Ndim) {
            pa0 = *reinterpret_cast<const float4*>(Arow + k0 + 16);
            pa1 = *reinterpret_cast<const float4*>(Arow + k0 + 20);
            pa2 = *reinterpret_cast<const float4*>(Arow + k0 + 24);
            pa3 = *reinterpret_cast<const float4*>(Arow + k0 + 28);
            pb  = *reinterpret_cast<const float4*>(Bp + (size_t)(k0 + 16) * (Tdim * CCAT));
        }
#pragma unroll
        for (int kk = 0; kk < 16; kk++) {
            float4 af0 = *reinterpret_cast<const float4*>(&As[kk][tm * 8]);
            float4 af1 = *reinterpret_cast<const float4*>(&As[kk][tm * 8 + 4]);
            const uint64_t* bp64 = reinterpret_cast<const uint64_t*>(&Bs[kk][tn * 8]);
            uint64_t b0 = bp64[0], b1 = bp64[1], b2 = bp64[2], b3 = bp64[3];
            uint64_t ap[8];
            ap[0] = pack2(af0.x, af0.x); ap[1] = pack2(af0.y, af0.y);
            ap[2] = pack2(af0.z, af0.z); ap[3] = pack2(af0.w, af0.w);
            ap[4] = pack2(af1.x, af1.x); ap[5] = pack2(af1.y, af1.y);
            ap[6] = pack2(af1.z, af1.z); ap[7] = pack2(af1.w, af1.w);
#pragma unroll
            for (int i = 0; i < 8; i++) {
                fma2(acc[i][0], ap[i], b0);
                fma2(acc[i][1], ap[i], b1);
                fma2(acc[i][2], ap[i], b2);
                fma2(acc[i][3], ap[i], b3);
            }
        }
        __syncthreads();
    }
#pragma unroll
    for (int i = 0; i < 8; i++) {
        int j = j0 + tm * 8 + i;
        int kb = j >> 9, w = j & 511;
        float* out = g_Hfull + ((size_t)b * NT + w * Tdim + t) * CCAT
                   + Cdim + kb * Cdim + tn * 8;
        float2 c0 = unpack2(acc[i][0]), c1 = unpack2(acc[i][1]);
        float2 c2 = unpack2(acc[i][2]), c3 = unpack2(acc[i][3]);
        *reinterpret_cast<float4*>(out)     = make_float4(c0.x, c0.y, c1.x, c1.y);
        *reinterpret_cast<float4*>(out + 4) = make_float4(c2.x, c2.y, c3.x, c3.y);
    }
}

// ---------- GEMM2: y[m][o] = sum_f Hfull[m][f] * Wt[f][o] + bias[o] ----------
// M=393216 rows ordered (b,n,t); Mtile=128, Ntile=64, Kt=16; 128 threads, 8x8.
__global__ __launch_bounds__(128, 4) void gemm2_kernel(const float* __restrict__ bias,
                                                       float* __restrict__ y) {
    const int m0 = blockIdx.x * 128;
    __shared__ float As[16][132];
    __shared__ float Bs[16][64];
    const int tid = threadIdx.x;
    const int tn = tid >> 4, tm = tid & 15;

    uint64_t acc[8][4];
#pragma unroll
    for (int i = 0; i < 8; i++)
#pragma unroll
        for (int q = 0; q < 4; q++) acc[i][q] = 0ull;

    const float* __restrict__ Arow = g_Hfull + (size_t)(m0 + tid) * CCAT;
    const int f0 = tid * 2;
    const int kkB0 = f0 >> 4, c4B0 = (f0 & 15) << 2;
    const int kkB1 = (f0 + 1) >> 4, c4B1 = ((f0 + 1) & 15) << 2;

    float4 pa0 = *reinterpret_cast<const float4*>(Arow + 0);
    float4 pa1 = *reinterpret_cast<const float4*>(Arow + 4);
    float4 pa2 = *reinterpret_cast<const float4*>(Arow + 8);
    float4 pa3 = *reinterpret_cast<const float4*>(Arow + 12);
    float4 pb0 = *reinterpret_cast<const float4*>(g_Wt + kkB0 * 64 + c4B0);
    float4 pb1 = *reinterpret_cast<const float4*>(g_Wt + kkB1 * 64 + c4B1);

    for (int k0 = 0; k0 < CCAT; k0 += 16) {
        As[0][tid]  = pa0.x; As[1][tid]  = pa0.y; As[2][tid]  = pa0.z; As[3][tid]  = pa0.w;
        As[4][tid]  = pa1.x; As[5][tid]  = pa1.y; As[6][tid]  = pa1.z; As[7][tid]  = pa1.w;
        As[8][tid]  = pa2.x; As[9][tid]  = pa2.y; As[10][tid] = pa2.z; As[11][tid] = pa2.w;
        As[12][tid] = pa3.x; As[13][tid] = pa3.y; As[14][tid] = pa3.z; As[15][tid] = pa3.w;
        *reinterpret_cast<float4*>(&Bs[kkB0][c4B0]) = pb0;
        *reinterpret_cast<float4*>(&Bs[kkB1][c4B1]) = pb1;
        __syncthreads();
        if (k0 + 16 < CCAT) {
            pa0 = *reinterpret_cast<const float4*>(Arow + k0 + 16);
            pa1 = *reinterpret_cast<const float4*>(Arow + k0 + 20);
            pa2 = *reinterpret_cast<const float4*>(Arow + k0 + 24);
            pa3 = *reinterpret_cast<const float4*>(Arow + k0 + 28);
            pb0 = *reinterpret_cast<const float4*>(g_Wt + (k0 + 16 + kkB0) * 64 + c4B0);
            pb1 = *reinterpret_cast<const float4*>(g_Wt + (k0 + 16 + kkB1) * 64 + c4B1);
        }
#pragma unroll
        for (int kk = 0; kk < 16; kk++) {
            float a[8];
#pragma unroll
            for (int i = 0; i < 8; i++) a[i] = As[kk][tm + 16 * i];
            const uint64_t* bp64 = reinterpret_cast<const uint64_t*>(&Bs[kk][tn * 8]);
            uint64_t b0 = bp64[0], b1 = bp64[1], b2 = bp64[2], b3 = bp64[3];
#pragma unroll
            for (int i = 0; i < 8; i++) {
                uint64_t ap = pack2(a[i], a[i]);
                fma2(acc[i][0], ap, b0);
                fma2(acc[i][1], ap, b1);
                fma2(acc[i][2], ap, b2);
                fma2(acc[i][3], ap, b3);
            }
        }
        __syncthreads();
    }
    const int bb = m0 / NT;           // batch index (blocks never straddle b: 6144 % 128 == 0)
    const int r0 = m0 - bb * NT;
    float bv[8];
#pragma unroll
    for (int q = 0; q < 8; q++) bv[q] = bias[tn * 8 + q];
    float* ybase = y + (size_t)bb * (COUT * NT) + r0 + tm;
#pragma unroll
    for (int i = 0; i < 8; i++) {
        const int rr = 16 * i;
#pragma unroll
        for (int q = 0; q < 4; q++) {
            float2 c = unpack2(acc[i][q]);
            const int o0 = tn * 8 + 2 * q;
            ybase[(size_t)o0 * NT + rr]       = c.x + bv[2 * q];
            ybase[(size_t)(o0 + 1) * NT + rr] = c.y + bv[2 * q + 1];
        }
    }
}

extern "C" void kernel_launch(void* const* d_in, const int* in_sizes, int n_in,
                              void* d_out, int out_size) {
    const float* x        = (const float*)d_in[0];  // [64,64,512,12]
    const float* supports = (const float*)d_in[1];  // [2,512,512]
    const float* W        = (const float*)d_in[2];  // [64,320]
    const float* bias     = (const float*)d_in[3];  // [64]
    float* y = (float*)d_out;                       // [64,64,512,12]

    a2_kernel<<<dim3(8, 8, 2), 256>>>(supports);
    gt_kernel<<<dim3(16, 16, 4), 256>>>(supports);
    wt_kernel<<<dim3(80, 1, 1), 256>>>(W);
    transpose_kernel<<<dim3(64, 64), 256>>>(x);
    gemm1_kernel<<<dim3(8, 768), 256>>>();
    gemm2_kernel<<<dim3(3072), 128>>>(bias, y);
    (void)in_sizes; (void)n_in; (void)out_size;
}

// round 4
// speedup vs baseline: 1.9806x; 1.9806x over previous
#include <cuda_runtime.h>
#include <cuda_bf16.h>
#include <cstdint>

// GraphConv: y[b,o,n,t] = sum_f W[o,f] * h[b,f,n,t] + bias[o]
//   h = concat([x, x·A0, x·A0², x·A1, x·A1²], channel axis)
//
// Round-4 (= round-3 resubmit after infra failure; compute_100-safe tensor cores):
//   prep:  A0², A1² (fp32), Gt_hi/lo bf16 splits [2048 x 512],
//          Xb_hi/lo bf16 splits [b][768][512], Hfull identity block.
//   GEMM1: mma.sync.m16n8k16 bf16x3 (hh+hl+lh, fp32 reg accum):
//          per b: D[2048 x 768] = Gt @ Xb^T -> scatter into Hfull.
//   GEMM2: fp32 f32x2: y = Hfull[393216,320] @ Wt[320,64] + bias.

constexpr int Bdim = 64, Cdim = 64, Ndim = 512, Tdim = 12;
constexpr int CCAT = 320, COUT = 64;
constexpr int NT   = Ndim * Tdim;     // 6144
constexpr int JD   = 2048;            // 4 * Ndim
constexpr int NCOL = 768;             // Tdim * Cdim

__device__ float g_Hfull[(size_t)Bdim * NT * CCAT];       // ~503 MB
__device__ float g_A2[2 * Ndim * Ndim];
__device__ float g_Wt[CCAT * COUT];
__device__ __nv_bfloat16 g_Gt_hi[(size_t)JD * Ndim];
__device__ __nv_bfloat16 g_Gt_lo[(size_t)JD * Ndim];
__device__ __nv_bfloat16 g_Xb_hi[(size_t)Bdim * NCOL * Ndim];
__device__ __nv_bfloat16 g_Xb_lo[(size_t)Bdim * NCOL * Ndim];

// ===================== helpers =====================
__device__ __forceinline__ uint32_t smem_to_u32(const void* p) {
    uint32_t a;
    asm("{ .reg .u64 t; cvta.to.shared.u64 t, %1; cvt.u32.u64 %0, t; }" : "=r"(a) : "l"(p));
    return a;
}
__device__ __forceinline__ void cpasync16(uint32_t saddr, const void* g) {
    asm volatile("cp.async.cg.shared.global [%0], [%1], 16;" :: "r"(saddr), "l"(g));
}
__device__ __forceinline__ void ldsm4(uint32_t* r, uint32_t addr) {
    asm volatile("ldmatrix.sync.aligned.m8n8.x4.shared.b16 {%0,%1,%2,%3}, [%4];"
                 : "=r"(r[0]), "=r"(r[1]), "=r"(r[2]), "=r"(r[3]) : "r"(addr));
}
__device__ __forceinline__ void mma_bf16(float* c, const uint32_t* a, const uint32_t* b) {
    asm volatile("mma.sync.aligned.m16n8k16.row.col.f32.bf16.bf16.f32 "
                 "{%0,%1,%2,%3}, {%4,%5,%6,%7}, {%8,%9}, {%0,%1,%2,%3};"
                 : "+f"(c[0]), "+f"(c[1]), "+f"(c[2]), "+f"(c[3])
                 : "r"(a[0]), "r"(a[1]), "r"(a[2]), "r"(a[3]), "r"(b[0]), "r"(b[1]));
}
__device__ __forceinline__ uint64_t pack2(float lo, float hi) {
    uint64_t p;
    asm("mov.b64 %0, {%1, %2};" : "=l"(p) : "f"(lo), "f"(hi));
    return p;
}
__device__ __forceinline__ float2 unpack2(uint64_t p) {
    float2 r;
    asm("mov.b64 {%0, %1}, %2;" : "=f"(r.x), "=f"(r.y) : "l"(p));
    return r;
}
__device__ __forceinline__ void fma2(uint64_t& d, uint64_t a, uint64_t b) {
    asm("fma.rn.f32x2 %0, %1, %2, %0;" : "+l"(d) : "l"(a), "l"(b));
}
__device__ __forceinline__ void split_bf16(float a, __nv_bfloat16& hi, __nv_bfloat16& lo) {
    hi = __float2bfloat16(a);
    lo = __float2bfloat16(a - __bfloat162float(hi));
}

// ===================== prep: A2[e] = A_e @ A_e (fp32) =====================
__global__ __launch_bounds__(256) void a2_kernel(const float* __restrict__ S) {
    const int e = blockIdx.z;
    const float* __restrict__ A = S + e * Ndim * Ndim;
    const int r0 = blockIdx.y * 64, c0 = blockIdx.x * 64;
    __shared__ float As[16][64];
    __shared__ float Bs[16][64];
    const int tid = threadIdx.x;
    const int ty = tid >> 4, tx = tid & 15;
    float acc[4][4];
#pragma unroll
    for (int i = 0; i < 4; i++)
#pragma unroll
        for (int j = 0; j < 4; j++) acc[i][j] = 0.f;

    const int rrL = tid >> 2, k4L = (tid & 3) << 2;
    const int kkL = tid >> 4, c4L = (tid & 15) << 2;
    for (int k0 = 0; k0 < Ndim; k0 += 16) {
        float4 av = *reinterpret_cast<const float4*>(A + (r0 + rrL) * Ndim + k0 + k4L);
        As[k4L + 0][rrL] = av.x; As[k4L + 1][rrL] = av.y;
        As[k4L + 2][rrL] = av.z; As[k4L + 3][rrL] = av.w;
        *reinterpret_cast<float4*>(&Bs[kkL][c4L]) =
            *reinterpret_cast<const float4*>(A + (k0 + kkL) * Ndim + c0 + c4L);
        __syncthreads();
#pragma unroll
        for (int kk = 0; kk < 16; kk++) {
            float a[4], bb[4];
#pragma unroll
            for (int i = 0; i < 4; i++) a[i] = As[kk][ty * 4 + i];
#pragma unroll
            for (int j = 0; j < 4; j++) bb[j] = Bs[kk][tx * 4 + j];
#pragma unroll
            for (int i = 0; i < 4; i++)
#pragma unroll
                for (int j = 0; j < 4; j++) acc[i][j] += a[i] * bb[j];
        }
        __syncthreads();
    }
#pragma unroll
    for (int i = 0; i < 4; i++) {
        float4 v = make_float4(acc[i][0], acc[i][1], acc[i][2], acc[i][3]);
        *reinterpret_cast<float4*>(g_A2 + (size_t)e * Ndim * Ndim +
                                   (r0 + ty * 4 + i) * Ndim + c0 + tx * 4) = v;
    }
}

// ===================== prep: Gt_hi/lo[j=(k*512+w)][v] = split(M_k[v][w]) =====================
__global__ __launch_bounds__(256) void gt_kernel(const float* __restrict__ S) {
    const int k = blockIdx.z;
    const float* __restrict__ M = (k == 0) ? S
                                : (k == 1) ? g_A2
                                : (k == 2) ? (S + Ndim * Ndim)
                                           : (g_A2 + Ndim * Ndim);
    const int v0 = blockIdx.y * 32, w0 = blockIdx.x * 32;
    __shared__ float s[32][33];
    const int ty = threadIdx.x >> 5, tx = threadIdx.x & 31;   // 8 x 32
#pragma unroll
    for (int i = 0; i < 4; i++)
        s[ty + i * 8][tx] = M[(v0 + ty + i * 8) * Ndim + w0 + tx];
    __syncthreads();
#pragma unroll
    for (int i = 0; i < 4; i++) {
        float a = s[tx][ty + i * 8];
        __nv_bfloat16 hi, lo;
        split_bf16(a, hi, lo);
        size_t o = (size_t)(k * Ndim + w0 + ty + i * 8) * Ndim + v0 + tx;
        g_Gt_hi[o] = hi;
        g_Gt_lo[o] = lo;
    }
}

// ===================== prep: Wt[f][o] = W[o][f] =====================
__global__ void wt_kernel(const float* __restrict__ W) {
    int i = blockIdx.x * 256 + threadIdx.x;
    if (i < CCAT * COUT) {
        int f = i >> 6, o = i & 63;
        g_Wt[i] = W[o * CCAT + f];
    }
}

// ===================== prep: Xb_hi/lo[b][t*64+c][v] = split(x[b][c][v][t]) =====================
__global__ __launch_bounds__(128) void xprep_kernel(const float* __restrict__ x) {
    __shared__ float sx[128][13];
    const int b = blockIdx.z, c = blockIdx.y, v0 = blockIdx.x * 128;
    const float* __restrict__ src = x + ((size_t)(b * Cdim + c) * Ndim + v0) * Tdim;
    for (int i = threadIdx.x; i < 128 * Tdim; i += 128)
        sx[i / Tdim][i % Tdim] = src[i];
    __syncthreads();
    const int vv = threadIdx.x;
#pragma unroll
    for (int t = 0; t < Tdim; t++) {
        float a = sx[vv][t];
        __nv_bfloat16 hi, lo;
        split_bf16(a, hi, lo);
        size_t o = ((size_t)b * NCOL + t * Cdim + c) * Ndim + v0 + vv;
        g_Xb_hi[o] = hi;
        g_Xb_lo[o] = lo;
    }
}

// ===================== transpose: Hfull[b][n][t][0:64] = x[b][:,n,t] =====================
__global__ __launch_bounds__(256) void transpose_kernel(const float* __restrict__ x) {
    __shared__ float s[64][97];
    const int b = blockIdx.y;
    const int n0 = blockIdx.x * 8;
    const int tid = threadIdx.x;
    for (int i = tid; i < 64 * 96; i += 256) {
        int c = i / 96, r = i - c * 96;
        s[c][r] = x[((size_t)(b * 64 + c) * Ndim + n0) * Tdim + r];
    }
    __syncthreads();
    for (int i = tid; i < 96 * 64; i += 256) {
        int r = i >> 6, c = i & 63;
        g_Hfull[((size_t)b * NT + n0 * Tdim + r) * CCAT + c] = s[c][r];
    }
}

// ===================== GEMM1: mma.sync bf16x3 diffusion =====================
// Per b: D[2048 x 768] = Gt[2048x512] @ Xb[768x512]^T.
// CTA 128x128, BK=32, 8 warps (4x2), warp tile 32x64, double-buffered cp.async.
constexpr int G1_RS   = 80;                  // smem row stride bytes (32 bf16 + 16B pad)
constexpr int G1_TILE = 128 * G1_RS;         // 10240 B per operand tile
constexpr int G1_STAGE = 4 * G1_TILE;        // Ah, Al, Bh, Bl
constexpr int G1_SMEM = 2 * G1_STAGE;        // 81920 B

__global__ __launch_bounds__(256, 1) void gemm1_mma_kernel() {
    extern __shared__ char smem[];
    const uint32_t sb = smem_to_u32(smem);
    const int tid  = threadIdx.x;
    const int wid  = tid >> 5, lane = tid & 31;
    const int wm   = wid & 3;                 // 0..3 -> m offset wm*32
    const int wn   = wid >> 2;                // 0..1 -> n offset wn*64
    const int j0   = blockIdx.x * 128;
    const int n0   = blockIdx.y * 128;
    const int b    = blockIdx.z;

    const __nv_bfloat16* __restrict__ gAh = g_Gt_hi + (size_t)j0 * Ndim;
    const __nv_bfloat16* __restrict__ gAl = g_Gt_lo + (size_t)j0 * Ndim;
    const __nv_bfloat16* __restrict__ gBh = g_Xb_hi + ((size_t)b * NCOL + n0) * Ndim;
    const __nv_bfloat16* __restrict__ gBl = g_Xb_lo + ((size_t)b * NCOL + n0) * Ndim;

    // loader indices: 2 vectors (16B) per thread per tile
    const int r0v  = tid >> 2;                 // row for v = tid
    const int s0v  = tid & 3;                  // 16B segment
    const int r1v  = (tid + 256) >> 2;
    const int s1v  = (tid + 256) & 3;

    auto load_stage = [&](int it, int stg) {
        const int kc = it * 32;
        const uint32_t sB = sb + stg * G1_STAGE;
        // Ah
        cpasync16(sB + 0 * G1_TILE + r0v * G1_RS + s0v * 16, gAh + (size_t)r0v * Ndim + kc + s0v * 8);
        cpasync16(sB + 0 * G1_TILE + r1v * G1_RS + s1v * 16, gAh + (size_t)r1v * Ndim + kc + s1v * 8);
        // Al
        cpasync16(sB + 1 * G1_TILE + r0v * G1_RS + s0v * 16, gAl + (size_t)r0v * Ndim + kc + s0v * 8);
        cpasync16(sB + 1 * G1_TILE + r1v * G1_RS + s1v * 16, gAl + (size_t)r1v * Ndim + kc + s1v * 8);
        // Bh
        cpasync16(sB + 2 * G1_TILE + r0v * G1_RS + s0v * 16, gBh + (size_t)r0v * Ndim + kc + s0v * 8);
        cpasync16(sB + 2 * G1_TILE + r1v * G1_RS + s1v * 16, gBh + (size_t)r1v * Ndim + kc + s1v * 8);
        // Bl
        cpasync16(sB + 3 * G1_TILE + r0v * G1_RS + s0v * 16, gBl + (size_t)r0v * Ndim + kc + s0v * 8);
        cpasync16(sB + 3 * G1_TILE + r1v * G1_RS + s1v * 16, gBl + (size_t)r1v * Ndim + kc + s1v * 8);
    };

    float acc[2][8][4];
#pragma unroll
    for (int mi = 0; mi < 2; mi++)
#pragma unroll
        for (int ni = 0; ni < 8; ni++)
#pragma unroll
            for (int q = 0; q < 4; q++) acc[mi][ni][q] = 0.f;

    // ldmatrix per-lane offsets
    const int qa = lane >> 3;
    const int aoff = ((qa & 1) * 8 + (lane & 7)) * G1_RS + (qa >> 1) * 16;  // A x4
    const int boff = (qa >> 1) * 8 * G1_RS + (lane & 7) * G1_RS + (qa & 1) * 16;  // B pair x4

    load_stage(0, 0);
    asm volatile("cp.async.commit_group;");

    const int NK = Ndim / 32;   // 16
    for (int it = 0; it < NK; it++) {
        const int cur = it & 1;
        if (it + 1 < NK) {
            load_stage(it + 1, cur ^ 1);
            asm volatile("cp.async.commit_group;");
            asm volatile("cp.async.wait_group 1;");
        } else {
            asm volatile("cp.async.wait_group 0;");
        }
        __syncthreads();

        const uint32_t sAh = sb + cur * G1_STAGE + 0 * G1_TILE + (wm * 32) * G1_RS;
        const uint32_t sAl = sb + cur * G1_STAGE + 1 * G1_TILE + (wm * 32) * G1_RS;
        const uint32_t sBh = sb + cur * G1_STAGE + 2 * G1_TILE + (wn * 64) * G1_RS;
        const uint32_t sBl = sb + cur * G1_STAGE + 3 * G1_TILE + (wn * 64) * G1_RS;

#pragma unroll
        for (int k0 = 0; k0 < 32; k0 += 16) {
            uint32_t ah[2][4], al[2][4], bh[8][2], bl[8][2];
#pragma unroll
            for (int mi = 0; mi < 2; mi++) {
                ldsm4(ah[mi], sAh + mi * 16 * G1_RS + k0 * 2 + aoff);
                ldsm4(al[mi], sAl + mi * 16 * G1_RS + k0 * 2 + aoff);
            }
#pragma unroll
            for (int np = 0; np < 4; np++) {
                uint32_t t4[4];
                ldsm4(t4, sBh + np * 16 * G1_RS + k0 * 2 + boff);
                bh[2 * np][0] = t4[0]; bh[2 * np][1] = t4[1];
                bh[2 * np + 1][0] = t4[2]; bh[2 * np + 1][1] = t4[3];
                ldsm4(t4, sBl + np * 16 * G1_RS + k0 * 2 + boff);
                bl[2 * np][0] = t4[0]; bl[2 * np][1] = t4[1];
                bl[2 * np + 1][0] = t4[2]; bl[2 * np + 1][1] = t4[3];
            }
#pragma unroll
            for (int mi = 0; mi < 2; mi++)
#pragma unroll
                for (int ni = 0; ni < 8; ni++) {
                    mma_bf16(acc[mi][ni], ah[mi], bh[ni]);
                    mma_bf16(acc[mi][ni], ah[mi], bl[ni]);
                    mma_bf16(acc[mi][ni], al[mi], bh[ni]);
                }
        }
        __syncthreads();
    }

    // ---- epilogue: scatter into Hfull[b][w][t][64 + 64*kb + c] ----
    const int lrow = lane >> 2;          // 0..7
    const int lcol = (lane & 3) * 2;     // 0,2,4,6
#pragma unroll
    for (int mi = 0; mi < 2; mi++) {
#pragma unroll
        for (int ni = 0; ni < 8; ni++) {
            const int nv = n0 + wn * 64 + ni * 8 + lcol;
            const int t = nv >> 6, c = nv & 63;
#pragma unroll
            for (int half = 0; half < 2; half++) {
                const int j = j0 + wm * 32 + mi * 16 + lrow + half * 8;
                const int kb = j >> 9, w = j & 511;
                float* dst = g_Hfull + ((size_t)b * NT + (size_t)w * Tdim + t) * CCAT
                           + Cdim + kb * Cdim + c;
                *reinterpret_cast<float2*>(dst) =
                    make_float2(acc[mi][ni][half * 2], acc[mi][ni][half * 2 + 1]);
            }
        }
    }
}

// ===================== GEMM2: y = Hfull @ Wt + bias (fp32 f32x2) =====================
__global__ __launch_bounds__(128, 4) void gemm2_kernel(const float* __restrict__ bias,
                                                       float* __restrict__ y) {
    const int m0 = blockIdx.x * 128;
    __shared__ float As[16][132];
    __shared__ float Bs[16][64];
    const int tid = threadIdx.x;
    const int tn = tid >> 4, tm = tid & 15;

    uint64_t acc[8][4];
#pragma unroll
    for (int i = 0; i < 8; i++)
#pragma unroll
        for (int q = 0; q < 4; q++) acc[i][q] = 0ull;

    const float* __restrict__ Arow = g_Hfull + (size_t)(m0 + tid) * CCAT;
    const int f0 = tid * 2;
    const int kkB0 = f0 >> 4, c4B0 = (f0 & 15) << 2;
    const int kkB1 = (f0 + 1) >> 4, c4B1 = ((f0 + 1) & 15) << 2;

    float4 pa0 = *reinterpret_cast<const float4*>(Arow + 0);
    float4 pa1 = *reinterpret_cast<const float4*>(Arow + 4);
    float4 pa2 = *reinterpret_cast<const float4*>(Arow + 8);
    float4 pa3 = *reinterpret_cast<const float4*>(Arow + 12);
    float4 pb0 = *reinterpret_cast<const float4*>(g_Wt + kkB0 * 64 + c4B0);
    float4 pb1 = *reinterpret_cast<const float4*>(g_Wt + kkB1 * 64 + c4B1);

    for (int k0 = 0; k0 < CCAT; k0 += 16) {
        As[0][tid]  = pa0.x; As[1][tid]  = pa0.y; As[2][tid]  = pa0.z; As[3][tid]  = pa0.w;
        As[4][tid]  = pa1.x; As[5][tid]  = pa1.y; As[6][tid]  = pa1.z; As[7][tid]  = pa1.w;
        As[8][tid]  = pa2.x; As[9][tid]  = pa2.y; As[10][tid] = pa2.z; As[11][tid] = pa2.w;
        As[12][tid] = pa3.x; As[13][tid] = pa3.y; As[14][tid] = pa3.z; As[15][tid] = pa3.w;
        *reinterpret_cast<float4*>(&Bs[kkB0][c4B0]) = pb0;
        *reinterpret_cast<float4*>(&Bs[kkB1][c4B1]) = pb1;
        __syncthreads();
        if (k0 + 16 < CCAT) {
            pa0 = *reinterpret_cast<const float4*>(Arow + k0 + 16);
            pa1 = *reinterpret_cast<const float4*>(Arow + k0 + 20);
            pa2 = *reinterpret_cast<const float4*>(Arow + k0 + 24);
            pa3 = *reinterpret_cast<const float4*>(Arow + k0 + 28);
            pb0 = *reinterpret_cast<const float4*>(g_Wt + (k0 + 16 + kkB0) * 64 + c4B0);
            pb1 = *reinterpret_cast<const float4*>(g_Wt + (k0 + 16 + kkB1) * 64 + c4B1);
        }
#pragma unroll
        for (int kk = 0; kk < 16; kk++) {
            float a[8];
#pragma unroll
            for (int i = 0; i < 8; i++) a[i] = As[kk][tm + 16 * i];
            const uint64_t* bp64 = reinterpret_cast<const uint64_t*>(&Bs[kk][tn * 8]);
            uint64_t b0 = bp64[0], b1 = bp64[1], b2 = bp64[2], b3 = bp64[3];
#pragma unroll
            for (int i = 0; i < 8; i++) {
                uint64_t ap = pack2(a[i], a[i]);
                fma2(acc[i][0], ap, b0);
                fma2(acc[i][1], ap, b1);
                fma2(acc[i][2], ap, b2);
                fma2(acc[i][3], ap, b3);
            }
        }
        __syncthreads();
    }
    const int bb = m0 / NT;
    const int r0 = m0 - bb * NT;
    float bv[8];
#pragma unroll
    for (int q = 0; q < 8; q++) bv[q] = bias[tn * 8 + q];
    float* ybase = y + (size_t)bb * (COUT * NT) + r0 + tm;
#pragma unroll
    for (int i = 0; i < 8; i++) {
        const int rr = 16 * i;
#pragma unroll
        for (int q = 0; q < 4; q++) {
            float2 c = unpack2(acc[i][q]);
            const int o0 = tn * 8 + 2 * q;
            ybase[(size_t)o0 * NT + rr]       = c.x + bv[2 * q];
            ybase[(size_t)(o0 + 1) * NT + rr] = c.y + bv[2 * q + 1];
        }
    }
}

extern "C" void kernel_launch(void* const* d_in, const int* in_sizes, int n_in,
                              void* d_out, int out_size) {
    const float* x        = (const float*)d_in[0];  // [64,64,512,12]
    const float* supports = (const float*)d_in[1];  // [2,512,512]
    const float* W        = (const float*)d_in[2];  // [64,320]
    const float* bias     = (const float*)d_in[3];  // [64]
    float* y = (float*)d_out;                       // [64,64,512,12]

    cudaFuncSetAttribute(gemm1_mma_kernel,
                         cudaFuncAttributeMaxDynamicSharedMemorySize, G1_SMEM);

    a2_kernel<<<dim3(8, 8, 2), 256>>>(supports);
    gt_kernel<<<dim3(16, 16, 4), 256>>>(supports);
    wt_kernel<<<dim3(80, 1, 1), 256>>>(W);
    xprep_kernel<<<dim3(4, 64, 64), 128>>>(x);
    transpose_kernel<<<dim3(64, 64), 256>>>(x);
    gemm1_mma_kernel<<<dim3(16, 6, 64), 256, G1_SMEM>>>();
    gemm2_kernel<<<dim3(3072), 128>>>(bias, y);
    (void)in_sizes; (void)n_in; (void)out_size;
}